// round 4
// baseline (speedup 1.0000x reference)
#include <cuda_runtime.h>
#include <cstdint>

// IndRNN recurrent-only: h_t = relu(x_t + w * h_{t-1})
// x: [T=2048, B=64, H=512] f32, w: [H], out: [T,B,H] f32. 512MB traffic floor.
// R4: per-warp LDG queue cap (~55) limits register-path MLP to ~7MB chip-wide.
// Bypass with cp.async -> SMEM ring (no depth cap). Each thread consumes only
// its own cp.asyncs => no __syncthreads, per-thread wait_group pipeline.
// In-flight: 5 stages x 32 t x 4B x 32768 thr ~= 20MB.

#define T_LEN 2048
#define B_DIM 64
#define H_DIM 512
#define NCH (B_DIM * H_DIM)   // 32768 chains
#define TPB 224               // 147 CTAs -> 1 CTA/SM, single wave
#define U 32                  // timesteps per stage
#define NSTAGE 6              // 6*32*224*4 = 172032 B dynamic smem
#define NTILES (T_LEN / U)    // 64
#define SMEM_BYTES (NSTAGE * U * TPB * 4)

__device__ __forceinline__ void cp_async4(uint32_t saddr, const float* gptr) {
    asm volatile("cp.async.ca.shared.global [%0], [%1], 4;"
                 :: "r"(saddr), "l"(gptr));
}

__global__ __launch_bounds__(TPB, 1)
void indrnn_scan_kernel(const float* __restrict__ x,
                        const float* __restrict__ w,
                        float* __restrict__ out) {
    extern __shared__ float smem[];

    const int tid = threadIdx.x;
    const int idx = blockIdx.x * TPB + tid;
    if (idx >= NCH) return;   // safe: no block-wide sync anywhere

    const float wv = w[idx & (H_DIM - 1)];
    const float* xp = x + idx;
    float* op = out + idx;
    float h = 0.0f;

    // Per-thread shared column base (element stride TPB, conflict-free)
    const uint32_t s_col = (uint32_t)__cvta_generic_to_shared(smem + tid);

    // Prologue: fill NSTAGE-1 stages
    #pragma unroll
    for (int p = 0; p < NSTAGE - 1; ++p) {
        const float* g = xp + (size_t)p * U * NCH;
        const uint32_t sb = s_col + (uint32_t)(p * U * TPB) * 4u;
        #pragma unroll
        for (int u = 0; u < U; ++u)
            cp_async4(sb + (uint32_t)(u * TPB) * 4u, g + (size_t)u * NCH);
        asm volatile("cp.async.commit_group;");
    }

    for (int tile = 0; tile < NTILES; ++tile) {
        // Issue stage tile+NSTAGE-1 (empty commit past the end keeps counts aligned)
        const int ft = tile + NSTAGE - 1;
        if (ft < NTILES) {
            const int s = ft % NSTAGE;
            const float* g = xp + (size_t)ft * U * NCH;
            const uint32_t sb = s_col + (uint32_t)(s * U * TPB) * 4u;
            #pragma unroll
            for (int u = 0; u < U; ++u)
                cp_async4(sb + (uint32_t)(u * TPB) * 4u, g + (size_t)u * NCH);
        }
        asm volatile("cp.async.commit_group;");

        // Oldest stage (this tile) complete for THIS thread
        asm volatile("cp.async.wait_group %0;" :: "n"(NSTAGE - 1));

        const int s = tile % NSTAGE;
        const float* sp = smem + (size_t)s * U * TPB + tid;
        float* ob = op + (size_t)tile * U * NCH;
        #pragma unroll
        for (int u = 0; u < U; ++u) {
            h = fmaxf(fmaf(wv, h, sp[(size_t)u * TPB]), 0.0f);
            __stcs(ob + (size_t)u * NCH, h);
        }
    }
}

extern "C" void kernel_launch(void* const* d_in, const int* in_sizes, int n_in,
                              void* d_out, int out_size) {
    const float* x = (const float*)d_in[0];
    const float* w = (const float*)d_in[1];
    float* out = (float*)d_out;

    cudaFuncSetAttribute(indrnn_scan_kernel,
                         cudaFuncAttributeMaxDynamicSharedMemorySize, SMEM_BYTES);

    const int grid = (NCH + TPB - 1) / TPB;  // 147
    indrnn_scan_kernel<<<grid, TPB, SMEM_BYTES>>>(x, w, out);
}

// round 5
// speedup vs baseline: 1.1279x; 1.1279x over previous
#include <cuda_runtime.h>
#include <cstdint>

// IndRNN recurrent-only: h_t = relu(x_t + w * h_{t-1})
// x: [T=2048, B=64, H=512] f32. 512MB traffic floor (~73us @7TB/s).
// R5: 4 chains/thread (float4). cp.async.cg 16B -> SMEM ring (bypass LDG queue
// cap AND L1), LDS.128, STG.128. 4x fewer LSU ops; ~23MB in flight.
// No __syncthreads needed: each thread consumes only its own cp.asyncs.

#define T_LEN 2048
#define B_DIM 64
#define H_DIM 512
#define NCH (B_DIM * H_DIM)     // 32768 chains
#define VEC 4
#define NTHREADS (NCH / VEC)    // 8192
#define TPB 64
#define GRID (NTHREADS / TPB)   // 128 CTAs, 1/SM
#define U 16                    // timesteps per stage
#define NSTAGE 12
#define NTILES (T_LEN / U)      // 128
#define SMEM_BYTES (NSTAGE * U * TPB * 16)  // 196608

__device__ __forceinline__ void cp_async16(uint32_t saddr, const void* gptr) {
    asm volatile("cp.async.cg.shared.global [%0], [%1], 16;"
                 :: "r"(saddr), "l"(gptr));
}

__global__ __launch_bounds__(TPB, 1)
void indrnn_scan_kernel(const float* __restrict__ x,
                        const float* __restrict__ w,
                        float* __restrict__ out) {
    extern __shared__ float4 smem4[];

    const int tid = threadIdx.x;
    const int cid = blockIdx.x * TPB + tid;      // 0..8191, owns chains 4cid..4cid+3

    // 4 consecutive h-dims: (4*cid) mod 512
    const float4 wv = *reinterpret_cast<const float4*>(w + ((cid & (H_DIM / VEC - 1)) << 2));

    const float4* xp = reinterpret_cast<const float4*>(x) + cid;   // stride NCH/4 per t
    float4* op = reinterpret_cast<float4*>(out) + cid;
    const int stride4 = NCH / VEC;               // 8192 float4 per timestep

    float4 h = make_float4(0.f, 0.f, 0.f, 0.f);

    const uint32_t s_col = (uint32_t)__cvta_generic_to_shared(smem4 + tid);

    // Prologue: fill NSTAGE-1 stages
    #pragma unroll
    for (int p = 0; p < NSTAGE - 1; ++p) {
        const float4* g = xp + (size_t)p * U * stride4;
        const uint32_t sb = s_col + (uint32_t)(p * U * TPB) * 16u;
        #pragma unroll
        for (int u = 0; u < U; ++u)
            cp_async16(sb + (uint32_t)(u * TPB) * 16u, g + (size_t)u * stride4);
        asm volatile("cp.async.commit_group;");
    }

    for (int tile = 0; tile < NTILES; ++tile) {
        // Issue stage tile+NSTAGE-1 (empty commit past end keeps group count aligned)
        const int ft = tile + NSTAGE - 1;
        if (ft < NTILES) {
            const int s = ft % NSTAGE;
            const float4* g = xp + (size_t)ft * U * stride4;
            const uint32_t sb = s_col + (uint32_t)(s * U * TPB) * 16u;
            #pragma unroll
            for (int u = 0; u < U; ++u)
                cp_async16(sb + (uint32_t)(u * TPB) * 16u, g + (size_t)u * stride4);
        }
        asm volatile("cp.async.commit_group;");

        // Oldest stage (this tile) complete for THIS thread
        asm volatile("cp.async.wait_group %0;" :: "n"(NSTAGE - 1));

        const int s = tile % NSTAGE;
        const float4* sp = smem4 + (size_t)s * U * TPB + tid;
        float4* ob = op + (size_t)tile * U * stride4;
        #pragma unroll
        for (int u = 0; u < U; ++u) {
            float4 v = sp[(size_t)u * TPB];
            h.x = fmaxf(fmaf(wv.x, h.x, v.x), 0.0f);
            h.y = fmaxf(fmaf(wv.y, h.y, v.y), 0.0f);
            h.z = fmaxf(fmaf(wv.z, h.z, v.z), 0.0f);
            h.w = fmaxf(fmaf(wv.w, h.w, v.w), 0.0f);
            __stcs(ob + (size_t)u * stride4, h);
        }
    }
}

extern "C" void kernel_launch(void* const* d_in, const int* in_sizes, int n_in,
                              void* d_out, int out_size) {
    const float* x = (const float*)d_in[0];
    const float* w = (const float*)d_in[1];
    float* out = (float*)d_out;

    cudaFuncSetAttribute(indrnn_scan_kernel,
                         cudaFuncAttributeMaxDynamicSharedMemorySize, SMEM_BYTES);

    indrnn_scan_kernel<<<GRID, TPB, SMEM_BYTES>>>(x, w, out);
}